// round 7
// baseline (speedup 1.0000x reference)
#include <cuda_runtime.h>
#include <cuda_bf16.h>
#include <math.h>

// Problem constants (match reference)
#define Mn 100000
#define Nn 14000
#define Hn 256
#define K1n 16
#define K2n 32
#define Kn 48          // K1+K2
#define Cn 7
#define Bn 64
#define PER_CLASS 2000  // N // C
#define EPSF 1e-8f

typedef unsigned long long u64t;

// ---- packed f32x2 helpers (sm_103a; ptxas never emits these from C++) ----
__device__ __forceinline__ u64t ffma2(u64t a, u64t b, u64t c) {
    u64t d;
    asm("fma.rn.f32x2 %0, %1, %2, %3;" : "=l"(d) : "l"(a), "l"(b), "l"(c));
    return d;
}
__device__ __forceinline__ u64t fmul2(u64t a, u64t b) {
    u64t d;
    asm("mul.rn.f32x2 %0, %1, %2;" : "=l"(d) : "l"(a), "l"(b));
    return d;
}
__device__ __forceinline__ u64t fadd2(u64t a, u64t b) {
    u64t d;
    asm("add.rn.f32x2 %0, %1, %2;" : "=l"(d) : "l"(a), "l"(b));
    return d;
}
__device__ __forceinline__ u64t pack2(float lo, float hi) {
    u64t r;
    asm("mov.b64 %0, {%1, %2};" : "=l"(r) : "f"(lo), "f"(hi));
    return r;
}
__device__ __forceinline__ float2 u2f(u64t v) {
    float2 r;
    asm("mov.b64 {%0, %1}, %2;" : "=f"(r.x), "=f"(r.y) : "l"(v));
    return r;
}

// Scratch (allocation-free rule: __device__ globals)
__device__ float g_inputs[(size_t)Nn * Hn];     // 14.3 MB
__device__ float g_rawret[(size_t)Nn * Hn];     // 14.3 MB
__device__ float g_class_sum[Cn * Hn];
__device__ float g_ave[Cn * Hn];
__device__ float g_ave_norm[Cn];

// ---------------------------------------------------------------------------
// Kernel 0: zero class accumulators (graph replays reuse device globals)
// ---------------------------------------------------------------------------
__global__ void k_zero() {
    int i = blockIdx.x * blockDim.x + threadIdx.x;
    if (i < Cn * Hn) g_class_sum[i] = 0.0f;
}

__device__ __forceinline__ float dot8(float4 a0, float4 a1, float4 b0, float4 b1) {
    float d = a0.x * b0.x;
    d = fmaf(a0.y, b0.y, d);
    d = fmaf(a0.z, b0.z, d);
    d = fmaf(a0.w, b0.w, d);
    d = fmaf(a1.x, b1.x, d);
    d = fmaf(a1.y, b1.y, d);
    d = fmaf(a1.z, b1.z, d);
    d = fmaf(a1.w, b1.w, d);
    return d;
}

// ---------------------------------------------------------------------------
// Kernel 1: one block (128 threads, 4 warps) per row n.
// Gather + cosine attention + softmax + weighted sum. Writes g_inputs only.
// Dynamic smem: u64 ex2[48]; f32 nbv[48*256], ce[256], sims[48], ex[48], redA[4]
// ---------------------------------------------------------------------------
#define RW_SMEM_BYTES (Kn * 8 + (Kn * Hn + Hn + Kn + Kn + 4) * 4)

// one neighbor: apply weight, stage to smem, cos-sim numerator/denominator
__device__ __forceinline__ void do_neighbor(
    int k, int row, int lane,
    const float* __restrict__ embeds,
    const u64t* wv,          // this lane's 8 weight floats (4 packed)
    const u64t* ce2r,        // this lane's 8 ce floats (4 packed)
    float ce_norm,
    float* nbv, float* sims)
{
    const float4* er = (const float4*)(embeds + (size_t)row * Hn);
    float4 ea = er[lane];
    float4 eb = er[32 + lane];
    const u64t* pe = (const u64t*)&ea;
    const u64t* pf = (const u64t*)&eb;
    u64t va[4];
    va[0] = fmul2(wv[0], pe[0]);
    va[1] = fmul2(wv[1], pe[1]);
    va[2] = fmul2(wv[2], pf[0]);
    va[3] = fmul2(wv[3], pf[1]);
    // stage as two float4 stores
    float4 s0, s1;
    ((u64t*)&s0)[0] = va[0]; ((u64t*)&s0)[1] = va[1];
    ((u64t*)&s1)[0] = va[2]; ((u64t*)&s1)[1] = va[3];
    ((float4*)&nbv[k * Hn])[lane]      = s0;
    ((float4*)&nbv[k * Hn])[32 + lane] = s1;
    // packed dot products
    u64t d2 = 0ull, q2 = 0ull;
    #pragma unroll
    for (int i = 0; i < 4; ++i) {
        d2 = ffma2(va[i], ce2r[i], d2);
        q2 = ffma2(va[i], va[i], q2);
    }
    float2 dd = u2f(d2), qq = u2f(q2);
    float d = dd.x + dd.y;
    float q = qq.x + qq.y;
    #pragma unroll
    for (int o = 16; o; o >>= 1) {
        d += __shfl_xor_sync(0xffffffffu, d, o);
        q += __shfl_xor_sync(0xffffffffu, q, o);
    }
    if (lane == 0)
        sims[k] = d / (ce_norm * fmaxf(sqrtf(q), EPSF));
}

__global__ __launch_bounds__(128, 4) void k_rows(
    const float* __restrict__ embeds,
    const float* __restrict__ w_self,
    const float* __restrict__ w_n,
    const float* __restrict__ w_n2,
    const int* __restrict__ idx,
    const int* __restrict__ nbr,
    const int* __restrict__ nbr2)
{
    extern __shared__ u64t smu[];
    u64t* ex2   = smu;                 // [48]
    float* nbv  = (float*)(ex2 + Kn);  // [48][256]
    float* ce   = nbv + Kn * Hn;       // [256]
    float* sims = ce + Hn;             // [48]
    float* ex   = sims + Kn;           // [48]
    float* redA = ex + Kn;             // [4]

    const int n    = blockIdx.x;
    const int t    = threadIdx.x;
    const int lane = t & 31;
    const int w    = t >> 5;

    const int center = idx[n];

    // ---- Phase A (packed): ce = w_self * embeds[center]; ||ce|| ----
    {
        const u64t* er2 = (const u64t*)(embeds + (size_t)center * Hn);
        const u64t* ws2 = (const u64t*)w_self;
        u64t v2 = fmul2(ws2[t], er2[t]);      // t covers pairs (2t, 2t+1)
        ((u64t*)ce)[t] = v2;
        u64t cn2 = ffma2(v2, v2, 0ull);
        float2 cc = u2f(cn2);
        float cn = cc.x + cc.y;
        #pragma unroll
        for (int o = 16; o; o >>= 1) cn += __shfl_xor_sync(0xffffffffu, cn, o);
        if (lane == 0) redA[w] = cn;
    }
    __syncthreads();
    const float ce_norm = fmaxf(sqrtf(redA[0] + redA[1] + redA[2] + redA[3]), EPSF);

    // Per-lane packed copies of ce and the two neighbor prompt weights
    u64t ce2r[4], wnr[4], wn2r[4];
    {
        const u64t* cp  = (const u64t*)ce;
        const u64t* wp  = (const u64t*)w_n;
        const u64t* wp2 = (const u64t*)w_n2;
        ce2r[0] = cp[lane * 2];      ce2r[1] = cp[lane * 2 + 1];
        ce2r[2] = cp[64 + lane * 2]; ce2r[3] = cp[64 + lane * 2 + 1];
        wnr[0] = wp[lane * 2];       wnr[1] = wp[lane * 2 + 1];
        wnr[2] = wp[64 + lane * 2];  wnr[3] = wp[64 + lane * 2 + 1];
        wn2r[0] = wp2[lane * 2];     wn2r[1] = wp2[lane * 2 + 1];
        wn2r[2] = wp2[64 + lane * 2];wn2r[3] = wp2[64 + lane * 2 + 1];
    }

    // ---- Phase B: warp w handles k = w + 4j; j<4 -> hop1, j>=4 -> hop2 ----
    // unroll 2: keeps cross-iteration MLP without blowing the 6KB L0 I$.
    #pragma unroll 2
    for (int j = 0; j < 4; ++j) {
        const int k = w + 4 * j;
        const int row = nbr[n * K1n + k];
        do_neighbor(k, row, lane, embeds, wnr, ce2r, ce_norm, nbv, sims);
    }
    #pragma unroll 2
    for (int j = 4; j < 12; ++j) {
        const int k = w + 4 * j;
        const int row = nbr2[n * K2n + (k - K1n)];
        do_neighbor(k, row, lane, embeds, wn2r, ce2r, ce_norm, nbv, sims);
    }
    __syncthreads();

    // ---- Phase C: softmax over 48 sims ----
    float mx = -1e30f;
    #pragma unroll
    for (int k = 0; k < Kn; ++k) mx = fmaxf(mx, sims[k]);
    if (t < Kn) {
        float e = expf(sims[t] - mx);
        ex[t] = e;
        ex2[t] = pack2(e, e);
    }
    __syncthreads();
    float ssum = 0.0f;
    #pragma unroll
    for (int k = 0; k < Kn; ++k) ssum += ex[k];
    const float inv = 1.0f / ssum;

    // ---- Phase D: inputs = (sum_k ex_k*nbv_k)*inv + ce -> g_inputs (packed) --
    {
        const u64t* nbv2 = (const u64t*)nbv;
        const u64t* ce2s = (const u64t*)ce;
        u64t acc = 0ull;
        #pragma unroll 8
        for (int k = 0; k < Kn; ++k)
            acc = ffma2(ex2[k], nbv2[k * 128 + t], acc);
        u64t r2 = ffma2(acc, pack2(inv, inv), ce2s[t]);
        ((u64t*)(g_inputs + (size_t)n * Hn))[t] = r2;
    }
}

// ---------------------------------------------------------------------------
// Kernel 2: adapter as register-tiled batched GEMM.
// rawret = elu(inputs @ W1 + b1) @ W2 + b2 + ce ; ce recomputed from embeds.
// Per-block smem class accumulation -> 1792 global atomics per block.
// Smem: As 64x260 f32, Hs 64x68 f32, cls 7x256 f32, meta 128 int  = 91648 B
// ---------------------------------------------------------------------------
#define AT_TILE 64
#define AS_LD 260
#define HS_LD 68
#define AD_SMEM_BYTES ((AT_TILE * AS_LD + AT_TILE * HS_LD + Cn * Hn) * 4 + AT_TILE * 2 * 4)

__global__ __launch_bounds__(256, 2) void k_adapter(
    const float* __restrict__ embeds,
    const float* __restrict__ w_self,
    const float* __restrict__ W1,
    const float* __restrict__ b1,
    const float* __restrict__ W2,
    const float* __restrict__ b2,
    const int* __restrict__ idx,
    const int* __restrict__ labels)
{
    extern __shared__ float sm[];
    float* As  = sm;                     // [64][260]
    float* Hs  = As + AT_TILE * AS_LD;   // [64][68]
    float* cls = Hs + AT_TILE * HS_LD;   // [7][256]
    int*  lbls = (int*)(cls + Cn * Hn);  // [64]
    int*  ctrs = lbls + AT_TILE;         // [64]

    const int r0 = blockIdx.x * AT_TILE;
    const int t  = threadIdx.x;
    const int rg = t >> 4;   // 0..15 -> rows 4rg..4rg+3
    const int cq = t & 15;   // E1: cols 4cq..4cq+3 ; E2: cols 16cq..16cq+15

    // ---- zero class accumulator; stage per-row meta; stage inputs tile ----
    #pragma unroll
    for (int i = t; i < Cn * Hn; i += 256) cls[i] = 0.0f;
    if (t < AT_TILE) {
        const int row = r0 + t;
        lbls[t] = (row < Nn) ? labels[row] : 0;
        ctrs[t] = (row < Nn) ? idx[row]    : 0;
    }
    #pragma unroll
    for (int i = t; i < AT_TILE * 64; i += 256) {   // float4 granularity
        int row = i >> 6;
        int c4  = i & 63;
        float4 v = make_float4(0.f, 0.f, 0.f, 0.f);
        if (r0 + row < Nn)
            v = ((const float4*)(g_inputs + (size_t)(r0 + row) * Hn))[c4];
        ((float4*)(As + row * AS_LD))[c4] = v;
    }
    __syncthreads();

    // ---- E1: h1 = elu(A @ W1 + b1), micro-tile 4 rows x 4 cols ----
    {
        u64t acc[4][2] = {{0ull,0ull},{0ull,0ull},{0ull,0ull},{0ull,0ull}};
        const u64t* W1p = (const u64t*)W1;
        #pragma unroll 4
        for (int k = 0; k < Hn; ++k) {
            const u64t w0 = W1p[k * 32 + 2 * cq];
            const u64t w1 = W1p[k * 32 + 2 * cq + 1];
            #pragma unroll
            for (int i = 0; i < 4; ++i) {
                float a = As[(4 * rg + i) * AS_LD + k];
                u64t as = pack2(a, a);
                acc[i][0] = ffma2(as, w0, acc[i][0]);
                acc[i][1] = ffma2(as, w1, acc[i][1]);
            }
        }
        const u64t* b1p = (const u64t*)b1;
        const u64t bb0 = b1p[2 * cq], bb1 = b1p[2 * cq + 1];
        #pragma unroll
        for (int i = 0; i < 4; ++i) {
            float2 z0 = u2f(fadd2(acc[i][0], bb0));
            float2 z1 = u2f(fadd2(acc[i][1], bb1));
            float4 hv;
            hv.x = z0.x > 0.f ? z0.x : expm1f(z0.x);
            hv.y = z0.y > 0.f ? z0.y : expm1f(z0.y);
            hv.z = z1.x > 0.f ? z1.x : expm1f(z1.x);
            hv.w = z1.y > 0.f ? z1.y : expm1f(z1.y);
            // ((4rg+i)*68 + 4cq)*4 is 16B-aligned (272 = 17*16)
            *(float4*)&Hs[(4 * rg + i) * HS_LD + 4 * cq] = hv;
        }
    }
    __syncthreads();

    // ---- E2: rawret = h1 @ W2 + b2 + ce, micro-tile 4 rows x 16 cols ----
    {
        u64t acc2[4][8];
        #pragma unroll
        for (int i = 0; i < 4; ++i)
            #pragma unroll
            for (int j = 0; j < 8; ++j) acc2[i][j] = 0ull;

        const u64t* W2p = (const u64t*)W2;
        #pragma unroll 2
        for (int b = 0; b < Bn; ++b) {
            u64t wv[8];
            #pragma unroll
            for (int j = 0; j < 8; ++j) wv[j] = W2p[b * 128 + 8 * cq + j];
            #pragma unroll
            for (int i = 0; i < 4; ++i) {
                float a = Hs[(4 * rg + i) * HS_LD + b];
                u64t as = pack2(a, a);
                #pragma unroll
                for (int j = 0; j < 8; ++j)
                    acc2[i][j] = ffma2(as, wv[j], acc2[i][j]);
            }
        }

        const u64t* b2p = (const u64t*)b2;
        const u64t* ws2 = (const u64t*)w_self;
        #pragma unroll
        for (int i = 0; i < 4; ++i) {
            const int row = r0 + 4 * rg + i;
            if (row >= Nn) continue;
            const int label  = lbls[4 * rg + i];
            const int center = ctrs[4 * rg + i];
            const u64t* er2 = (const u64t*)(embeds + (size_t)center * Hn);
            u64t* outp = (u64t*)(g_rawret + (size_t)row * Hn);
            #pragma unroll
            for (int j = 0; j < 8; ++j) {
                const int hp = 8 * cq + j;
                u64t ce2 = fmul2(ws2[hp], er2[hp]);   // recompute ce
                u64t r2 = fadd2(fadd2(acc2[i][j], b2p[hp]), ce2);
                outp[hp] = r2;
                float2 rr = u2f(r2);
                atomicAdd(&cls[label * Hn + 2 * hp],     rr.x);
                atomicAdd(&cls[label * Hn + 2 * hp + 1], rr.y);
            }
        }
    }
    __syncthreads();

    // ---- flush block-local class sums (1792 global atomics) ----
    #pragma unroll
    for (int i = t; i < Cn * Hn; i += 256)
        atomicAdd(&g_class_sum[i], cls[i]);
}

// ---------------------------------------------------------------------------
// Kernel 3: ave = class_sum / 2000; per-class norms. One block per class.
// ---------------------------------------------------------------------------
__global__ void k_ave() {
    __shared__ float rs[256];
    const int c = blockIdx.x;
    const int t = threadIdx.x;
    float v = g_class_sum[c * Hn + t] * (1.0f / (float)PER_CLASS);
    g_ave[c * Hn + t] = v;
    rs[t] = v * v;
    __syncthreads();
    #pragma unroll
    for (int s = 128; s; s >>= 1) {
        if (t < s) rs[t] += rs[t + s];
        __syncthreads();
    }
    if (t == 0) g_ave_norm[c] = fmaxf(sqrtf(rs[0]), EPSF);
}

// ---------------------------------------------------------------------------
// Kernel 4: ret[n,c] = softmax_c cos(rawret[n], ave[c]); one warp per row
// ---------------------------------------------------------------------------
__global__ __launch_bounds__(256) void k_ret(float* __restrict__ out) {
    __shared__ float av[Cn * Hn];
    __shared__ float an[Cn];
    const int t = threadIdx.x;
    for (int i = t; i < Cn * Hn; i += 256) av[i] = g_ave[i];
    if (t < Cn) an[t] = g_ave_norm[t];
    __syncthreads();

    const int lane = t & 31;
    const int wrp  = t >> 5;
    const int n = blockIdx.x * 8 + wrp;
    if (n >= Nn) return;

    const float4* r = (const float4*)(g_rawret + (size_t)n * Hn);
    const float4 ra = r[lane];
    const float4 rb = r[32 + lane];
    float nrm = dot8(ra, rb, ra, rb);
    float d[Cn];
    #pragma unroll
    for (int c = 0; c < Cn; ++c) {
        const float4* a = (const float4*)(av + c * Hn);
        d[c] = dot8(ra, rb, a[lane], a[32 + lane]);
    }
    #pragma unroll
    for (int o = 16; o; o >>= 1) {
        nrm += __shfl_xor_sync(0xffffffffu, nrm, o);
        #pragma unroll
        for (int c = 0; c < Cn; ++c) d[c] += __shfl_xor_sync(0xffffffffu, d[c], o);
    }
    const float rn = fmaxf(sqrtf(nrm), EPSF);
    float e[Cn], mx = -1e30f, s = 0.0f;
    #pragma unroll
    for (int c = 0; c < Cn; ++c) {
        d[c] = d[c] / (rn * an[c]);
        mx = fmaxf(mx, d[c]);
    }
    #pragma unroll
    for (int c = 0; c < Cn; ++c) { e[c] = expf(d[c] - mx); s += e[c]; }
    const float inv = 1.0f / s;
    if (lane == 0) {
        #pragma unroll
        for (int c = 0; c < Cn; ++c) out[n * Cn + c] = e[c] * inv;
    }
}

// ---------------------------------------------------------------------------
extern "C" void kernel_launch(void* const* d_in, const int* in_sizes, int n_in,
                              void* d_out, int out_size) {
    const float* embeds = (const float*)d_in[0];   // [M,H]
    const float* w_self = (const float*)d_in[1];   // [1,H]
    const float* w_n    = (const float*)d_in[2];   // [1,H]
    const float* w_n2   = (const float*)d_in[3];   // [1,H]
    const float* W1     = (const float*)d_in[4];   // [H,B]
    const float* b1     = (const float*)d_in[5];   // [B]
    const float* W2     = (const float*)d_in[6];   // [B,H]
    const float* b2     = (const float*)d_in[7];   // [H]
    const int*   idx    = (const int*)d_in[8];     // [N]
    const int*   nbr    = (const int*)d_in[9];     // [N,K1]
    const int*   nbr2   = (const int*)d_in[10];    // [N,K2]
    const int*   labels = (const int*)d_in[11];    // [N]
    float* out = (float*)d_out;                    // [N,C] float32

    cudaFuncSetAttribute(k_rows, cudaFuncAttributeMaxDynamicSharedMemorySize,
                         RW_SMEM_BYTES);
    cudaFuncSetAttribute(k_adapter, cudaFuncAttributeMaxDynamicSharedMemorySize,
                         AD_SMEM_BYTES);

    k_zero<<<(Cn * Hn + 255) / 256, 256>>>();
    k_rows<<<Nn, 128, RW_SMEM_BYTES>>>(embeds, w_self, w_n, w_n2,
                                       idx, nbr, nbr2);
    k_adapter<<<(Nn + AT_TILE - 1) / AT_TILE, 256, AD_SMEM_BYTES>>>(
        embeds, w_self, W1, b1, W2, b2, idx, labels);
    k_ave<<<Cn, 256>>>();
    k_ret<<<(Nn + 7) / 8, 256>>>(out);
}

// round 11
// speedup vs baseline: 1.3833x; 1.3833x over previous
#include <cuda_runtime.h>
#include <cuda_bf16.h>
#include <math.h>

// Problem constants (match reference)
#define Mn 100000
#define Nn 14000
#define Hn 256
#define K1n 16
#define K2n 32
#define Kn 48          // K1+K2
#define Cn 7
#define Bn 64
#define PER_CLASS 2000  // N // C
#define EPSF 1e-8f

typedef unsigned long long u64t;

// ---- packed f32x2 helpers (sm_103a; ptxas never emits these from C++) ----
__device__ __forceinline__ u64t ffma2(u64t a, u64t b, u64t c) {
    u64t d;
    asm("fma.rn.f32x2 %0, %1, %2, %3;" : "=l"(d) : "l"(a), "l"(b), "l"(c));
    return d;
}
__device__ __forceinline__ u64t fmul2(u64t a, u64t b) {
    u64t d;
    asm("mul.rn.f32x2 %0, %1, %2;" : "=l"(d) : "l"(a), "l"(b));
    return d;
}
__device__ __forceinline__ u64t fadd2(u64t a, u64t b) {
    u64t d;
    asm("add.rn.f32x2 %0, %1, %2;" : "=l"(d) : "l"(a), "l"(b));
    return d;
}
__device__ __forceinline__ u64t pack2(float lo, float hi) {
    u64t r;
    asm("mov.b64 %0, {%1, %2};" : "=l"(r) : "f"(lo), "f"(hi));
    return r;
}
__device__ __forceinline__ float2 u2f(u64t v) {
    float2 r;
    asm("mov.b64 {%0, %1}, %2;" : "=f"(r.x), "=f"(r.y) : "l"(v));
    return r;
}

// Scratch (allocation-free rule: __device__ globals)
__device__ float g_inputs[(size_t)Nn * Hn];     // 14.3 MB
__device__ float g_rawret[(size_t)Nn * Hn];     // 14.3 MB
__device__ float g_class_sum[Cn * Hn];
__device__ float g_ave[Cn * Hn];
__device__ float g_ave_norm[Cn];

// ---------------------------------------------------------------------------
// Kernel 0: zero class accumulators (graph replays reuse device globals)
// ---------------------------------------------------------------------------
__global__ void k_zero() {
    int i = blockIdx.x * blockDim.x + threadIdx.x;
    if (i < Cn * Hn) g_class_sum[i] = 0.0f;
}

__device__ __forceinline__ float dot8(float4 a0, float4 a1, float4 b0, float4 b1) {
    float d = a0.x * b0.x;
    d = fmaf(a0.y, b0.y, d);
    d = fmaf(a0.z, b0.z, d);
    d = fmaf(a0.w, b0.w, d);
    d = fmaf(a1.x, b1.x, d);
    d = fmaf(a1.y, b1.y, d);
    d = fmaf(a1.z, b1.z, d);
    d = fmaf(a1.w, b1.w, d);
    return d;
}

// ---------------------------------------------------------------------------
// Kernel 1: one block (128 threads, 4 warps) per row n.
// Gather + cosine attention + softmax + weighted sum. Writes g_inputs only.
// Dynamic smem: u64 ex2[48]; f32 nbv[48*256], ce[256], sims[48], ex[48], redA[4]
// ---------------------------------------------------------------------------
#define RW_SMEM_BYTES (Kn * 8 + (Kn * Hn + Hn + Kn + Kn + 4) * 4)

// Process a batch of 6 preloaded neighbors: weight+stage+partial dots, then
// ALL 12 shfl-reduction chains interleaved (critical path ~130 cyc, not 6x260).
__device__ __forceinline__ void comp_batch(
    int jb, int w, int lane,
    const float4* ea, const float4* eb,
    const u64t* wnr, const u64t* wn2r, const u64t* ce2r, float ce_norm,
    float* nbv, float* sims)
{
    float dv[6], qv[6];
    #pragma unroll
    for (int u = 0; u < 6; ++u) {
        const int j = jb + u;
        const u64t* wv = (j < 4) ? wnr : wn2r;   // compile-time select
        const int k = w + 4 * j;
        const u64t* pe = (const u64t*)&ea[u];
        const u64t* pf = (const u64t*)&eb[u];
        u64t va[4];
        va[0] = fmul2(wv[0], pe[0]);
        va[1] = fmul2(wv[1], pe[1]);
        va[2] = fmul2(wv[2], pf[0]);
        va[3] = fmul2(wv[3], pf[1]);
        float4 s0, s1;
        ((u64t*)&s0)[0] = va[0]; ((u64t*)&s0)[1] = va[1];
        ((u64t*)&s1)[0] = va[2]; ((u64t*)&s1)[1] = va[3];
        ((float4*)&nbv[k * Hn])[lane]      = s0;
        ((float4*)&nbv[k * Hn])[32 + lane] = s1;
        u64t d2 = 0ull, q2 = 0ull;
        #pragma unroll
        for (int i = 0; i < 4; ++i) {
            d2 = ffma2(va[i], ce2r[i], d2);
            q2 = ffma2(va[i], va[i], q2);
        }
        float2 dd = u2f(d2), qq = u2f(q2);
        dv[u] = dd.x + dd.y;
        qv[u] = qq.x + qq.y;
    }
    // 12 independent shfl chains, explicitly interleaved
    #pragma unroll
    for (int o = 16; o; o >>= 1) {
        #pragma unroll
        for (int u = 0; u < 6; ++u) {
            dv[u] += __shfl_xor_sync(0xffffffffu, dv[u], o);
            qv[u] += __shfl_xor_sync(0xffffffffu, qv[u], o);
        }
    }
    if (lane == 0) {
        #pragma unroll
        for (int u = 0; u < 6; ++u) {
            const int k = w + 4 * (jb + u);
            sims[k] = dv[u] / (ce_norm * fmaxf(sqrtf(qv[u]), EPSF));
        }
    }
}

__global__ __launch_bounds__(128) void k_rows(
    const float* __restrict__ embeds,
    const float* __restrict__ w_self,
    const float* __restrict__ w_n,
    const float* __restrict__ w_n2,
    const int* __restrict__ idx,
    const int* __restrict__ nbr,
    const int* __restrict__ nbr2)
{
    extern __shared__ u64t smu[];
    u64t* ex2   = smu;                 // [48]
    float* nbv  = (float*)(ex2 + Kn);  // [48][256]
    float* ce   = nbv + Kn * Hn;       // [256]
    float* sims = ce + Hn;             // [48]
    float* ex   = sims + Kn;           // [48]
    float* redA = ex + Kn;             // [4]

    const int n    = blockIdx.x;
    const int t    = threadIdx.x;
    const int lane = t & 31;
    const int w    = t >> 5;

    const int center = idx[n];

    // ---- hoist ALL neighbor indices for this warp (breaks idx->row dep) ----
    int rows[12];
    #pragma unroll
    for (int j = 0; j < 4; ++j)  rows[j] = nbr [n * K1n + w + 4 * j];
    #pragma unroll
    for (int j = 4; j < 12; ++j) rows[j] = nbr2[n * K2n + (w + 4 * j - K1n)];

    // ---- batch-0 gather issues NOW; latency hides under Phase A ----
    float4 ea0[6], eb0[6];
    #pragma unroll
    for (int u = 0; u < 6; ++u) {
        const float4* er = (const float4*)(embeds + (size_t)rows[u] * Hn);
        ea0[u] = er[lane];
        eb0[u] = er[32 + lane];
    }

    // ---- Phase A (packed): ce = w_self * embeds[center]; ||ce|| ----
    {
        const u64t* er2 = (const u64t*)(embeds + (size_t)center * Hn);
        const u64t* ws2 = (const u64t*)w_self;
        u64t v2 = fmul2(ws2[t], er2[t]);      // t covers pairs (2t, 2t+1)
        ((u64t*)ce)[t] = v2;
        u64t cn2 = ffma2(v2, v2, 0ull);
        float2 cc = u2f(cn2);
        float cn = cc.x + cc.y;
        #pragma unroll
        for (int o = 16; o; o >>= 1) cn += __shfl_xor_sync(0xffffffffu, cn, o);
        if (lane == 0) redA[w] = cn;
    }
    __syncthreads();
    const float ce_norm = fmaxf(sqrtf(redA[0] + redA[1] + redA[2] + redA[3]), EPSF);

    // Per-lane packed copies of ce and the two neighbor prompt weights
    u64t ce2r[4], wnr[4], wn2r[4];
    {
        const u64t* cp  = (const u64t*)ce;
        const u64t* wp  = (const u64t*)w_n;
        const u64t* wp2 = (const u64t*)w_n2;
        ce2r[0] = cp[lane * 2];      ce2r[1] = cp[lane * 2 + 1];
        ce2r[2] = cp[64 + lane * 2]; ce2r[3] = cp[64 + lane * 2 + 1];
        wnr[0] = wp[lane * 2];       wnr[1] = wp[lane * 2 + 1];
        wnr[2] = wp[64 + lane * 2];  wnr[3] = wp[64 + lane * 2 + 1];
        wn2r[0] = wp2[lane * 2];     wn2r[1] = wp2[lane * 2 + 1];
        wn2r[2] = wp2[64 + lane * 2];wn2r[3] = wp2[64 + lane * 2 + 1];
    }

    // ---- batch-1 gather issues BEFORE batch-0 compute (pipelined) ----
    float4 ea1[6], eb1[6];
    #pragma unroll
    for (int u = 0; u < 6; ++u) {
        const float4* er = (const float4*)(embeds + (size_t)rows[6 + u] * Hn);
        ea1[u] = er[lane];
        eb1[u] = er[32 + lane];
    }

    comp_batch(0, w, lane, ea0, eb0, wnr, wn2r, ce2r, ce_norm, nbv, sims);
    comp_batch(6, w, lane, ea1, eb1, wnr, wn2r, ce2r, ce_norm, nbv, sims);
    __syncthreads();

    // ---- Phase C: softmax over 48 sims ----
    float mx = -1e30f;
    #pragma unroll
    for (int k = 0; k < Kn; ++k) mx = fmaxf(mx, sims[k]);
    if (t < Kn) {
        float e = __expf(sims[t] - mx);
        ex[t] = e;
        ex2[t] = pack2(e, e);
    }
    __syncthreads();
    float ssum = 0.0f;
    #pragma unroll
    for (int k = 0; k < Kn; ++k) ssum += ex[k];
    const float inv = 1.0f / ssum;

    // ---- Phase D: inputs = (sum_k ex_k*nbv_k)*inv + ce -> g_inputs (packed) --
    {
        const u64t* nbv2 = (const u64t*)nbv;
        const u64t* ce2s = (const u64t*)ce;
        u64t acc = 0ull;
        #pragma unroll 8
        for (int k = 0; k < Kn; ++k)
            acc = ffma2(ex2[k], nbv2[k * 128 + t], acc);
        u64t r2 = ffma2(acc, pack2(inv, inv), ce2s[t]);
        ((u64t*)(g_inputs + (size_t)n * Hn))[t] = r2;
    }
}

// ---------------------------------------------------------------------------
// Kernel 2: adapter as register-tiled batched GEMM.
// rawret = elu(inputs @ W1 + b1) @ W2 + b2 + ce ; ce recomputed from embeds.
// Per-block smem class accumulation -> 1792 global atomics per block.
// Smem: As 64x260 f32, Hs 64x68 f32, cls 7x256 f32, meta 128 int  = 91648 B
// ---------------------------------------------------------------------------
#define AT_TILE 64
#define AS_LD 260
#define HS_LD 68
#define AD_SMEM_BYTES ((AT_TILE * AS_LD + AT_TILE * HS_LD + Cn * Hn) * 4 + AT_TILE * 2 * 4)

__global__ __launch_bounds__(256, 2) void k_adapter(
    const float* __restrict__ embeds,
    const float* __restrict__ w_self,
    const float* __restrict__ W1,
    const float* __restrict__ b1,
    const float* __restrict__ W2,
    const float* __restrict__ b2,
    const int* __restrict__ idx,
    const int* __restrict__ labels)
{
    extern __shared__ float sm[];
    float* As  = sm;                     // [64][260]
    float* Hs  = As + AT_TILE * AS_LD;   // [64][68]
    float* cls = Hs + AT_TILE * HS_LD;   // [7][256]
    int*  lbls = (int*)(cls + Cn * Hn);  // [64]
    int*  ctrs = lbls + AT_TILE;         // [64]

    const int r0 = blockIdx.x * AT_TILE;
    const int t  = threadIdx.x;
    const int rg = t >> 4;   // 0..15 -> rows 4rg..4rg+3
    const int cq = t & 15;   // E1: cols 4cq..4cq+3 ; E2: cols 16cq..16cq+15

    // ---- zero class accumulator; stage per-row meta; stage inputs tile ----
    #pragma unroll
    for (int i = t; i < Cn * Hn; i += 256) cls[i] = 0.0f;
    if (t < AT_TILE) {
        const int row = r0 + t;
        lbls[t] = (row < Nn) ? labels[row] : 0;
        ctrs[t] = (row < Nn) ? idx[row]    : 0;
    }
    #pragma unroll
    for (int i = t; i < AT_TILE * 64; i += 256) {   // float4 granularity
        int row = i >> 6;
        int c4  = i & 63;
        float4 v = make_float4(0.f, 0.f, 0.f, 0.f);
        if (r0 + row < Nn)
            v = ((const float4*)(g_inputs + (size_t)(r0 + row) * Hn))[c4];
        ((float4*)(As + row * AS_LD))[c4] = v;
    }
    __syncthreads();

    // ---- E1: h1 = elu(A @ W1 + b1), micro-tile 4 rows x 4 cols ----
    {
        u64t acc[4][2] = {{0ull,0ull},{0ull,0ull},{0ull,0ull},{0ull,0ull}};
        const float4* W1v = (const float4*)W1;   // row k: 16 float4
        #pragma unroll 4
        for (int k = 0; k < Hn; ++k) {
            float4 wf = W1v[k * 16 + cq];        // one LDG.128
            const u64t w0 = ((const u64t*)&wf)[0];
            const u64t w1 = ((const u64t*)&wf)[1];
            #pragma unroll
            for (int i = 0; i < 4; ++i) {
                float a = As[(4 * rg + i) * AS_LD + k];
                u64t as = pack2(a, a);
                acc[i][0] = ffma2(as, w0, acc[i][0]);
                acc[i][1] = ffma2(as, w1, acc[i][1]);
            }
        }
        const u64t* b1p = (const u64t*)b1;
        const u64t bb0 = b1p[2 * cq], bb1 = b1p[2 * cq + 1];
        #pragma unroll
        for (int i = 0; i < 4; ++i) {
            float2 z0 = u2f(fadd2(acc[i][0], bb0));
            float2 z1 = u2f(fadd2(acc[i][1], bb1));
            float4 hv;
            hv.x = z0.x > 0.f ? z0.x : expm1f(z0.x);
            hv.y = z0.y > 0.f ? z0.y : expm1f(z0.y);
            hv.z = z1.x > 0.f ? z1.x : expm1f(z1.x);
            hv.w = z1.y > 0.f ? z1.y : expm1f(z1.y);
            // ((4rg+i)*68 + 4cq)*4 is 16B-aligned (272 = 17*16)
            *(float4*)&Hs[(4 * rg + i) * HS_LD + 4 * cq] = hv;
        }
    }
    __syncthreads();

    // ---- E2: rawret = h1 @ W2 + b2 + ce, micro-tile 4 rows x 16 cols ----
    {
        u64t acc2[4][8];
        #pragma unroll
        for (int i = 0; i < 4; ++i)
            #pragma unroll
            for (int j = 0; j < 8; ++j) acc2[i][j] = 0ull;

        const float4* W2v = (const float4*)W2;   // row b: 64 float4
        #pragma unroll 2
        for (int b = 0; b < Bn; ++b) {
            u64t wv[8];
            #pragma unroll
            for (int q = 0; q < 4; ++q) {        // 4 x LDG.128
                float4 wf = W2v[b * 64 + 4 * cq + q];
                wv[2 * q]     = ((const u64t*)&wf)[0];
                wv[2 * q + 1] = ((const u64t*)&wf)[1];
            }
            #pragma unroll
            for (int i = 0; i < 4; ++i) {
                float a = Hs[(4 * rg + i) * HS_LD + b];
                u64t as = pack2(a, a);
                #pragma unroll
                for (int j = 0; j < 8; ++j)
                    acc2[i][j] = ffma2(as, wv[j], acc2[i][j]);
            }
        }

        const u64t* b2p = (const u64t*)b2;
        const u64t* ws2 = (const u64t*)w_self;
        #pragma unroll
        for (int i = 0; i < 4; ++i) {
            const int row = r0 + 4 * rg + i;
            if (row >= Nn) continue;
            const int label  = lbls[4 * rg + i];
            const int center = ctrs[4 * rg + i];
            const u64t* er2 = (const u64t*)(embeds + (size_t)center * Hn);
            u64t* outp = (u64t*)(g_rawret + (size_t)row * Hn);
            #pragma unroll
            for (int j = 0; j < 8; ++j) {
                const int hp = 8 * cq + j;
                u64t ce2 = fmul2(ws2[hp], er2[hp]);   // recompute ce
                u64t r2 = fadd2(fadd2(acc2[i][j], b2p[hp]), ce2);
                outp[hp] = r2;
                float2 rr = u2f(r2);
                atomicAdd(&cls[label * Hn + 2 * hp],     rr.x);
                atomicAdd(&cls[label * Hn + 2 * hp + 1], rr.y);
            }
        }
    }
    __syncthreads();

    // ---- flush block-local class sums (1792 global atomics) ----
    #pragma unroll
    for (int i = t; i < Cn * Hn; i += 256)
        atomicAdd(&g_class_sum[i], cls[i]);
}

// ---------------------------------------------------------------------------
// Kernel 3: ave = class_sum / 2000; per-class norms. One block per class.
// ---------------------------------------------------------------------------
__global__ void k_ave() {
    __shared__ float rs[256];
    const int c = blockIdx.x;
    const int t = threadIdx.x;
    float v = g_class_sum[c * Hn + t] * (1.0f / (float)PER_CLASS);
    g_ave[c * Hn + t] = v;
    rs[t] = v * v;
    __syncthreads();
    #pragma unroll
    for (int s = 128; s; s >>= 1) {
        if (t < s) rs[t] += rs[t + s];
        __syncthreads();
    }
    if (t == 0) g_ave_norm[c] = fmaxf(sqrtf(rs[0]), EPSF);
}

// ---------------------------------------------------------------------------
// Kernel 4: ret[n,c] = softmax_c cos(rawret[n], ave[c]); one warp per row
// ---------------------------------------------------------------------------
__global__ __launch_bounds__(256) void k_ret(float* __restrict__ out) {
    __shared__ float av[Cn * Hn];
    __shared__ float an[Cn];
    const int t = threadIdx.x;
    for (int i = t; i < Cn * Hn; i += 256) av[i] = g_ave[i];
    if (t < Cn) an[t] = g_ave_norm[t];
    __syncthreads();

    const int lane = t & 31;
    const int wrp  = t >> 5;
    const int n = blockIdx.x * 8 + wrp;
    if (n >= Nn) return;

    const float4* r = (const float4*)(g_rawret + (size_t)n * Hn);
    const float4 ra = r[lane];
    const float4 rb = r[32 + lane];
    float nrm = dot8(ra, rb, ra, rb);
    float d[Cn];
    #pragma unroll
    for (int c = 0; c < Cn; ++c) {
        const float4* a = (const float4*)(av + c * Hn);
        d[c] = dot8(ra, rb, a[lane], a[32 + lane]);
    }
    #pragma unroll
    for (int o = 16; o; o >>= 1) {
        nrm += __shfl_xor_sync(0xffffffffu, nrm, o);
        #pragma unroll
        for (int c = 0; c < Cn; ++c) d[c] += __shfl_xor_sync(0xffffffffu, d[c], o);
    }
    const float rn = fmaxf(sqrtf(nrm), EPSF);
    float e[Cn], mx = -1e30f, s = 0.0f;
    #pragma unroll
    for (int c = 0; c < Cn; ++c) {
        d[c] = d[c] / (rn * an[c]);
        mx = fmaxf(mx, d[c]);
    }
    #pragma unroll
    for (int c = 0; c < Cn; ++c) { e[c] = __expf(d[c] - mx); s += e[c]; }
    const float inv = 1.0f / s;
    if (lane == 0) {
        #pragma unroll
        for (int c = 0; c < Cn; ++c) out[n * Cn + c] = e[c] * inv;
    }
}

// ---------------------------------------------------------------------------
extern "C" void kernel_launch(void* const* d_in, const int* in_sizes, int n_in,
                              void* d_out, int out_size) {
    const float* embeds = (const float*)d_in[0];   // [M,H]
    const float* w_self = (const float*)d_in[1];   // [1,H]
    const float* w_n    = (const float*)d_in[2];   // [1,H]
    const float* w_n2   = (const float*)d_in[3];   // [1,H]
    const float* W1     = (const float*)d_in[4];   // [H,B]
    const float* b1     = (const float*)d_in[5];   // [B]
    const float* W2     = (const float*)d_in[6];   // [B,H]
    const float* b2     = (const float*)d_in[7];   // [H]
    const int*   idx    = (const int*)d_in[8];     // [N]
    const int*   nbr    = (const int*)d_in[9];     // [N,K1]
    const int*   nbr2   = (const int*)d_in[10];    // [N,K2]
    const int*   labels = (const int*)d_in[11];    // [N]
    float* out = (float*)d_out;                    // [N,C] float32

    cudaFuncSetAttribute(k_rows, cudaFuncAttributeMaxDynamicSharedMemorySize,
                         RW_SMEM_BYTES);
    cudaFuncSetAttribute(k_adapter, cudaFuncAttributeMaxDynamicSharedMemorySize,
                         AD_SMEM_BYTES);

    k_zero<<<(Cn * Hn + 255) / 256, 256>>>();
    k_rows<<<Nn, 128, RW_SMEM_BYTES>>>(embeds, w_self, w_n, w_n2,
                                       idx, nbr, nbr2);
    k_adapter<<<(Nn + AT_TILE - 1) / AT_TILE, 256, AD_SMEM_BYTES>>>(
        embeds, w_self, W1, b1, W2, b2, idx, labels);
    k_ave<<<Cn, 256>>>();
    k_ret<<<(Nn + 7) / 8, 256>>>(out);
}